// round 8
// baseline (speedup 1.0000x reference)
#include <cuda_runtime.h>
#include <cuda_bf16.h>
#include <math_constants.h>
#include <cstdint>

#define N_BOXES   262144
#define STRIDE    85
#define N_CLASSES 80
#define CONF_THRES 0.8f
#define NMS_THRES  0.4f
#define MAX_DET    300
#define NSHARD    4
#define SHARDCAP  256
#define CAP       (NSHARD * SHARDCAP)   // 1024 slots per class
#define MAXKEEP   2048
#define FULLMASK  0xffffffffu
#define BOXES_PER_BLK 64

// ---------------- device scratch (all self-cleaning across graph replays) ----------------
__device__ int   g_cnt4[N_CLASSES * NSHARD];   // zeroed by k_nms after reading
__device__ float g_x1[N_CLASSES * CAP];
__device__ float g_y1[N_CLASSES * CAP];
__device__ float g_x2[N_CLASSES * CAP];
__device__ float g_y2[N_CLASSES * CAP];
__device__ float g_sc[N_CLASSES * CAP];        // empty slots stay 0.0 (< every real score)
__device__ float g_cf[N_CLASSES * CAP];

__device__ int   g_keep_n;                     // reset by last nms block AFTER uniform snapshot
__device__ int   g_done;                       // reset by last nms block AFTER uniform snapshot
__device__ float g_keep_score[MAXKEEP];
__device__ float g_keep_conf [MAXKEEP];
__device__ int   g_keep_cls  [MAXKEEP];

__device__ __forceinline__ bool before(float ak, int ai, float bk, int bi) {
    return (ak > bk) || (ak == bk && ai < bi);
}

// ---------------- kernel 1: streaming classify/bucket (one coalesced pass) ----------------
__global__ __launch_bounds__(256) void k_pass1(const float* __restrict__ det) {
    __shared__ __align__(16) float tile[BOXES_PER_BLK * STRIDE];   // 21760 B

    int t = threadIdx.x;
    int lane = t & 31;
    int wid  = t >> 5;

    // coalesced float4 streaming load of 64 rows (block tile is 16B-aligned: 21760 % 16 == 0)
    const float4* src = (const float4*)(det + (size_t)blockIdx.x * (BOXES_PER_BLK * STRIDE));
    float4* dst = (float4*)tile;
    for (int i = t; i < (BOXES_PER_BLK * STRIDE) / 4; i += 256)
        dst[i] = src[i];
    __syncthreads();

    int shard = blockIdx.x & (NSHARD - 1);

    #pragma unroll
    for (int i = 0; i < BOXES_PER_BLK / 8; i++) {
        int b = wid * (BOXES_PER_BLK / 8) + i;
        const float* row = tile + b * STRIDE;

        float obj = row[4];                      // warp-uniform smem broadcast
        if (obj < CONF_THRES) continue;

        float a  = row[lane];
        float b2 = row[lane + 32];
        float c2 = (lane < 21) ? row[lane + 64] : -1e30f;

        float bv = -1e30f; int bi = 0;
        if (lane >= 5)            { bv = a;  bi = lane - 5;  }
        if (b2 > bv)              { bv = b2; bi = lane + 27; }
        if (lane < 21 && c2 > bv) { bv = c2; bi = lane + 59; }

        #pragma unroll
        for (int off = 16; off; off >>= 1) {
            float ov = __shfl_down_sync(FULLMASK, bv, off);
            int   oi = __shfl_down_sync(FULLMASK, bi, off);
            if (ov > bv || (ov == bv && oi < bi)) { bv = ov; bi = oi; }
        }

        if (lane == 0) {
            float x = row[0], y = row[1], w = row[2], h = row[3];
            float conf  = bv;
            float score = __fmul_rn(obj, conf);
            float hw = __fmul_rn(w, 0.5f);
            float hh = __fmul_rn(h, 0.5f);
            int local = atomicAdd(&g_cnt4[bi * NSHARD + shard], 1);
            if (local < SHARDCAP) {
                int idx = bi * CAP + shard * SHARDCAP + local;
                g_x1[idx] = __fsub_rn(x, hw);
                g_y1[idx] = __fsub_rn(y, hh);
                g_x2[idx] = __fadd_rn(x, hw);
                g_y2[idx] = __fadd_rn(y, hh);
                g_sc[idx] = score;
                g_cf[idx] = conf;
            }
        }
    }
}

// ---------------- kernel 2: per-class NMS + fused final (last block) ----------------
__global__ __launch_bounds__(1024) void k_nms(float* __restrict__ out, int out_size) {
    __shared__ __align__(16) unsigned char s_raw[32768];
    __shared__ int scnt[NSHARD];

    // --- aliased layout ---
    float* SK    = (float*)(s_raw);
    int*   SI    = (int*)  (s_raw + 4096);
    int*   S_KEEP= (int*)  (s_raw);
    int*   S_WMIN= (int*)  (s_raw + 4096);
    int*   S_MISC= (int*)  (s_raw + 4352);
    float* SX1   = (float*)(s_raw + 8192);
    float* SY1   = (float*)(s_raw + 12288);
    float* SX2   = (float*)(s_raw + 16384);
    float* SY2   = (float*)(s_raw + 20480);
    float* SKEY  = (float*)(s_raw + 24576);
    float* SCONF = (float*)(s_raw + 28672);
    float* FK    = (float*)(s_raw);
    int*   FI    = (int*)  (s_raw + 8192);
    float* FCONF = (float*)(s_raw + 16384);
    int*   FCLS  = (int*)  (s_raw + 17664);
    float* FOUTC = (float*)(s_raw + 18944);
    float* FOUTP = (float*)(s_raw + 20224);

    int c = blockIdx.x;
    int t = threadIdx.x;
    int lane = t & 31;
    int wid  = t >> 5;
    int base = c * CAP;

    // read counts, then reset for the next replay (same-thread read-before-write, race-free)
    if (t < NSHARD) {
        int v = g_cnt4[c * NSHARD + t];
        scnt[t] = (v > SHARDCAP) ? SHARDCAP : v;
        g_cnt4[c * NSHARD + t] = 0;
    }
    __syncthreads();
    int n = scnt[0] + scnt[1] + scnt[2] + scnt[3];

    if (n > 0) {
        // ---- hybrid bitonic sort, M = 1024, (key desc, id asc) ----
        // empty slots hold 0.0 (never written; per-(class,shard) counts are
        // replay-invariant); every real score > 0 -> empties sort last
        float key = g_sc[base + t];
        int   id  = t;

        #pragma unroll
        for (int k = 2; k <= 1024; k <<= 1) {
            #pragma unroll
            for (int j = k >> 1; j > 0; j >>= 1) {
                bool dir  = ((t & k) == 0);
                bool iLow = ((t & j) == 0);
                float pk; int pi;
                if (j >= 32) {
                    SK[t] = key; SI[t] = id;
                    __syncthreads();
                    pk = SK[t ^ j]; pi = SI[t ^ j];
                    __syncthreads();
                } else {
                    pk = __shfl_xor_sync(FULLMASK, key, j);
                    pi = __shfl_xor_sync(FULLMASK, id,  j);
                }
                if (before(key, id, pk, pi) != (iLow == dir)) { key = pk; id = pi; }
            }
        }

        // ---- gather coords/conf in sorted order ----
        float bx1 = g_x1[base + id], by1 = g_y1[base + id];
        float bx2 = g_x2[base + id], by2 = g_y2[base + id];
        SKEY[t]  = key;
        SCONF[t] = g_cf[base + id];
        SX1[t] = bx1; SY1[t] = by1; SX2[t] = bx2; SY2[t] = by2;
        __syncthreads();   // retires SK/SI aliases before S_KEEP/S_WMIN use

        float a2 = __fmul_rn(__fadd_rn(__fsub_rn(bx2, bx1), 1.0f),
                             __fadd_rn(__fsub_rn(by2, by1), 1.0f));
        bool alive = (t < n);

        // ---- greedy loop: zero atomics, 1 barrier per pick ----
        int np = 0;           // uniform across block
        int cur = 0, par = 0;
        while (cur < n) {
            if (t == 0) S_KEEP[np] = cur;
            np++;

            float px1 = SX1[cur], py1 = SY1[cur], px2 = SX2[cur], py2 = SY2[cur];
            float pa  = __fmul_rn(__fadd_rn(__fsub_rn(px2, px1), 1.0f),
                                  __fadd_rn(__fsub_rn(py2, py1), 1.0f));

            int cand = n;
            if (alive && t > cur) {
                float xx1 = fmaxf(px1, bx1), yy1 = fmaxf(py1, by1);
                float xx2 = fminf(px2, bx2), yy2 = fminf(py2, by2);
                float iw  = fmaxf(__fadd_rn(__fsub_rn(xx2, xx1), 1.0f), 0.0f);
                float ih  = fmaxf(__fadd_rn(__fsub_rn(yy2, yy1), 1.0f), 0.0f);
                float inter = __fmul_rn(iw, ih);
                float den = __fadd_rn(__fsub_rn(__fadd_rn(pa, a2), inter), 1e-16f);
                float iou = __fdiv_rn(inter, den);
                if (iou > NMS_THRES) alive = false;
                else                 cand = t;
            }
            #pragma unroll
            for (int off = 16; off; off >>= 1)
                cand = min(cand, __shfl_xor_sync(FULLMASK, cand, off));
            if (lane == 0) S_WMIN[par * 32 + wid] = cand;
            __syncthreads();
            int v = S_WMIN[par * 32 + lane];
            #pragma unroll
            for (int off = 16; off; off >>= 1)
                v = min(v, __shfl_xor_sync(FULLMASK, v, off));
            cur = v;
            par ^= 1;
        }

        // ---- flush: one global atomic per class ----
        if (t == 0) S_MISC[0] = atomicAdd(&g_keep_n, np);
        __syncthreads();
        int kbase = S_MISC[0];
        if (t < np) {
            int q  = S_KEEP[t];
            int kk = kbase + t;
            if (kk < MAXKEEP) {
                g_keep_score[kk] = SKEY[q];
                g_keep_conf [kk] = SCONF[q];
                g_keep_cls  [kk] = c;
            }
        }
    }

    // ---- last-block-done handoff ----
    __threadfence();
    __syncthreads();
    if (t == 0) S_MISC[1] = (atomicAdd(&g_done, 1) == N_CLASSES - 1) ? 1 : 0;
    __syncthreads();
    if (!S_MISC[1]) return;   // uniform per block (shared read after barrier)
    __threadfence();

    // ================= final phase (last-finishing block) =================
    // RACE FIX (R7 bug): snapshot K in ALL threads, barrier, THEN reset.
    int K = g_keep_n; if (K > MAXKEEP) K = MAXKEEP;
    int Kc = (K < MAX_DET) ? K : MAX_DET;
    __syncthreads();   // uniform K snapshot; also retires nms smem aliases
    if (t == 0) { g_keep_n = 0; g_done = 0; }   // cross-replay reset, post-snapshot

    if (t < MAX_DET) { FOUTC[t] = 0.0f; FOUTP[t] = 0.0f; }

    if (K <= 1024) {
        int m = 32; while (m < K) m <<= 1;
        float key = -CUDART_INF_F; int id = t;
        if (t < K) key = g_keep_score[t];

        for (int k = 2; k <= m; k <<= 1) {
            for (int j = k >> 1; j > 0; j >>= 1) {
                if (j >= 32) {
                    if (t < m) { FK[t] = key; FI[t] = id; }
                    __syncthreads();
                    float pk = 0.0f; int pi = 0;
                    if (t < m) { pk = FK[t ^ j]; pi = FI[t ^ j]; }
                    __syncthreads();
                    if (t < m) {
                        bool dir  = ((t & k) == 0);
                        bool iLow = ((t & j) == 0);
                        if (before(key, id, pk, pi) != (iLow == dir)) { key = pk; id = pi; }
                    }
                } else if (t < m) {
                    float pk = __shfl_xor_sync(FULLMASK, key, j);
                    int   pi = __shfl_xor_sync(FULLMASK, id,  j);
                    bool dir  = ((t & k) == 0);
                    bool iLow = ((t & j) == 0);
                    if (before(key, id, pk, pi) != (iLow == dir)) { key = pk; id = pi; }
                }
            }
        }
        if (t < Kc) { FCONF[t] = g_keep_conf[id]; FCLS[t] = g_keep_cls[id]; }
    } else {
        float k0 = (t        < K) ? g_keep_score[t]        : -CUDART_INF_F;
        float k1 = (t + 1024 < K) ? g_keep_score[t + 1024] : -CUDART_INF_F;
        int   i0 = t, i1 = t + 1024;

        #pragma unroll
        for (int k = 2; k <= 2048; k <<= 1) {
            #pragma unroll
            for (int j = k >> 1; j > 0; j >>= 1) {
                if (j == 1024) {
                    if (!before(k0, i0, k1, i1)) {
                        float tk = k0; k0 = k1; k1 = tk;
                        int   ti = i0; i0 = i1; i1 = ti;
                    }
                } else if (j >= 32) {
                    FK[t] = k0; FI[t] = i0;
                    FK[t + 1024] = k1; FI[t + 1024] = i1;
                    __syncthreads();
                    float p0 = FK[t ^ j];          int q0 = FI[t ^ j];
                    float p1 = FK[(t ^ j) + 1024]; int q1 = FI[(t ^ j) + 1024];
                    __syncthreads();
                    bool iLow = ((t & j) == 0);
                    bool d0 = ((t & k) == 0);
                    bool d1 = (((t + 1024) & k) == 0);
                    if (before(k0, i0, p0, q0) != (iLow == d0)) { k0 = p0; i0 = q0; }
                    if (before(k1, i1, p1, q1) != (iLow == d1)) { k1 = p1; i1 = q1; }
                } else {
                    bool iLow = ((t & j) == 0);
                    bool d0 = ((t & k) == 0);
                    bool d1 = (((t + 1024) & k) == 0);
                    float p0 = __shfl_xor_sync(FULLMASK, k0, j);
                    int   q0 = __shfl_xor_sync(FULLMASK, i0, j);
                    float p1 = __shfl_xor_sync(FULLMASK, k1, j);
                    int   q1 = __shfl_xor_sync(FULLMASK, i1, j);
                    if (before(k0, i0, p0, q0) != (iLow == d0)) { k0 = p0; i0 = q0; }
                    if (before(k1, i1, p1, q1) != (iLow == d1)) { k1 = p1; i1 = q1; }
                }
            }
        }
        if (t < Kc) { FCONF[t] = g_keep_conf[i0]; FCLS[t] = g_keep_cls[i0]; }
    }
    __syncthreads();

    // conf re-rank over Kc <= 300 (conf desc, ties -> larger score-rank first)
    if (t < Kc) {
        float mc = FCONF[t];
        int pos = 0;
        for (int j = 0; j < Kc; j++) {
            float oc = FCONF[j];
            if ((oc > mc) || (oc == mc && j > t)) pos++;
        }
        FOUTC[pos] = (float)FCLS[t];
        FOUTP[pos] = mc;
    }
    __syncthreads();

    if (t < MAX_DET) {
        if (t < out_size)            out[t]           = FOUTC[t];
        if (MAX_DET + t < out_size)  out[MAX_DET + t] = FOUTP[t];
    }
}

// ---------------- launch ----------------
extern "C" void kernel_launch(void* const* d_in, const int* in_sizes, int n_in,
                              void* d_out, int out_size) {
    const float* det = (const float*)d_in[0];
    float* out = (float*)d_out;

    k_pass1<<<N_BOXES / BOXES_PER_BLK, 256>>>(det);
    k_nms<<<N_CLASSES, 1024>>>(out, out_size);
}